// round 5
// baseline (speedup 1.0000x reference)
#include <cuda_runtime.h>

#define B_TOT   16
#define CIN     64
#define COUT    64
#define S_LEN   1024
#define KW      3
#define STILE   32
#define POSN    (STILE + 2)     // 34 input positions per tile (halo of 1 each side)
#define BH      8               // batches per block (b-half)
#define OTILE   4               // outputs per thread
#define OGN     8               // o-groups (warps) per block
#define OBLK    (OGN * OTILE)   // 32 outputs per block (o-half)
#define NTHREADS 256
#define SMEM_FLOATS (CIN * BH * POSN)   // 64*8*34 = 17408 floats = 69632 B

__global__ void __launch_bounds__(NTHREADS, 1)
locon1d_kernel(const float* __restrict__ X,     // (B, Cin, S)
               const float* __restrict__ W,     // (Cout, Cin, S, K)
               const float* __restrict__ Bias,  // (Cout, S)
               float* __restrict__ Out)         // (B, Cout, S)
{
    extern __shared__ float shx[];   // layout: [c][b][pos]  -> (c*BH + b)*POSN + pos

    const int s0     = blockIdx.x * STILE;
    const int o0base = blockIdx.y * OBLK;
    const int b0     = blockIdx.z * BH;
    const int tid    = threadIdx.x;

    // Cooperative input tile load: shx[c][b][pos] = X[b0+b][c][s0-1+pos] (zero-padded).
    // Consecutive tid -> consecutive pos -> coalesced global reads (input is L2-resident).
    for (int i = tid; i < SMEM_FLOATS; i += NTHREADS) {
        int pos = i % POSN;
        int bc  = i / POSN;
        int b   = bc % BH;
        int c   = bc / BH;
        int sg  = s0 - 1 + pos;
        float v = 0.0f;
        if ((unsigned)sg < (unsigned)S_LEN)
            v = X[((size_t)(b0 + b) * CIN + c) * S_LEN + sg];
        shx[i] = v;
    }
    __syncthreads();

    const int sl = tid & 31;          // lane = consecutive s -> coalesced weight loads
    const int og = tid >> 5;          // warp id = o-group
    const int s  = s0 + sl;
    const int o0 = o0base + og * OTILE;

    // acc[j][b]: 4 outputs x 8 batches = 32 registers.
    float acc[OTILE][BH];
    #pragma unroll
    for (int j = 0; j < OTILE; j++) {
        float bv = Bias[(o0 + j) * S_LEN + s];
        #pragma unroll
        for (int b = 0; b < BH; b++) acc[j][b] = bv;
    }

    // Weight base for (o0, c=0, s, k=0). Per (o,c): 3 consecutive floats at s*3.
    const float* wbase = W + (size_t)o0 * (CIN * S_LEN * KW) + (size_t)s * KW;

    #pragma unroll 2
    for (int c = 0; c < CIN; c++) {
        // x window for this thread: 8 batches x 3 taps from shared (conflict-free:
        // lanes differ only in sl, which is the fastest smem dimension).
        float xr[BH][KW];
        const float* xc = shx + (size_t)(c * BH) * POSN + sl;
        #pragma unroll
        for (int b = 0; b < BH; b++) {
            #pragma unroll
            for (int k = 0; k < KW; k++)
                xr[b][k] = xc[b * POSN + k];
        }

        const float* wc = wbase + (size_t)c * (S_LEN * KW);
        #pragma unroll
        for (int j = 0; j < OTILE; j++) {
            const float* wj = wc + (size_t)j * (CIN * S_LEN * KW);
            float w0 = wj[0];
            float w1 = wj[1];
            float w2 = wj[2];
            #pragma unroll
            for (int b = 0; b < BH; b++) {
                acc[j][b] += w0 * xr[b][0];
                acc[j][b] += w1 * xr[b][1];
                acc[j][b] += w2 * xr[b][2];
            }
        }
    }

    // Store: lanes = consecutive s -> fully coalesced 128B stores per warp.
    #pragma unroll
    for (int j = 0; j < OTILE; j++) {
        #pragma unroll
        for (int b = 0; b < BH; b++) {
            Out[((size_t)(b0 + b) * COUT + (o0 + j)) * S_LEN + s] = acc[j][b];
        }
    }
}

extern "C" void kernel_launch(void* const* d_in, const int* in_sizes, int n_in,
                              void* d_out, int out_size) {
    const float* x    = (const float*)d_in[0];
    const float* w    = (const float*)d_in[1];
    const float* bias = (const float*)d_in[2];
    float* out        = (float*)d_out;

    const int smem_bytes = SMEM_FLOATS * (int)sizeof(float);  // 69632 B > 48K -> opt-in
    cudaFuncSetAttribute(locon1d_kernel,
                         cudaFuncAttributeMaxDynamicSharedMemorySize, smem_bytes);

    dim3 grid(S_LEN / STILE, COUT / OBLK, B_TOT / BH);  // (32, 2, 2) = 128 blocks
    locon1d_kernel<<<grid, NTHREADS, smem_bytes>>>(x, w, bias, out);
}